// round 11
// baseline (speedup 1.0000x reference)
#include <cuda_runtime.h>
#include <cuda_fp16.h>

#define HD   128     // head dim
#define TOPK 64
#define SQL  1024
#define SKV  4096
#define NH   16
#define KV_ELEMS (NH * SKV * HD)   // 8,388,608 per tensor

// fp16 copies of K and V (16 MB each)
__device__ __half2 g_k16[KV_ELEMS / 2];
__device__ __half2 g_v16[KV_ELEMS / 2];

// ---- Pre-pass: fp32 -> fp16 conversion of K and V (8 elems/thread) ----
__global__ __launch_bounds__(256)
void convert_kv_kernel(const float4* __restrict__ k, const float4* __restrict__ v) {
    const int i = blockIdx.x * blockDim.x + threadIdx.x;  // over KV_ELEMS/8
    uint4* kd = reinterpret_cast<uint4*>(g_k16);
    uint4* vd = reinterpret_cast<uint4*>(g_v16);

    float4 a0 = k[2 * i], a1 = k[2 * i + 1];
    __half2 k0 = __floats2half2_rn(a0.x, a0.y);
    __half2 k1 = __floats2half2_rn(a0.z, a0.w);
    __half2 k2 = __floats2half2_rn(a1.x, a1.y);
    __half2 k3 = __floats2half2_rn(a1.z, a1.w);
    uint4 kp;
    kp.x = *reinterpret_cast<unsigned*>(&k0);
    kp.y = *reinterpret_cast<unsigned*>(&k1);
    kp.z = *reinterpret_cast<unsigned*>(&k2);
    kp.w = *reinterpret_cast<unsigned*>(&k3);
    kd[i] = kp;

    float4 b0 = v[2 * i], b1 = v[2 * i + 1];
    __half2 v0 = __floats2half2_rn(b0.x, b0.y);
    __half2 v1 = __floats2half2_rn(b0.z, b0.w);
    __half2 v2 = __floats2half2_rn(b1.x, b1.y);
    __half2 v3 = __floats2half2_rn(b1.z, b1.w);
    uint4 vp;
    vp.x = *reinterpret_cast<unsigned*>(&v0);
    vp.y = *reinterpret_cast<unsigned*>(&v1);
    vp.z = *reinterpret_cast<unsigned*>(&v2);
    vp.w = *reinterpret_cast<unsigned*>(&v3);
    vd[i] = vp;
}

// ---- Main sparse-attention kernel ----
// Block = (h, sq). 4 warps; warp w owns topk entries [w*16, w*16+16).
// Lanes 0-15 process one row, lanes 16-31 a second row; each lane covers
// 8 head dims via one 16B load. 4-deep prefetch ring (MLP=4).
// Softmax is computed redundantly by ALL warps (distributed): removes the
// warp0 serialization, the weight table round-trip, and one barrier.
// Row indices are stashed in registers between the two gather loops.
__global__ __launch_bounds__(128, 9)
void dsa_sparse_attn_kernel(const float* __restrict__ q,
                            const int*   __restrict__ topk_indices,
                            const float* __restrict__ topk_scores,
                            float* __restrict__ out) {
    const int sq   = blockIdx.x;
    const int h    = blockIdx.y;
    const int tid  = threadIdx.x;      // 0..127
    const int lane = tid & 31;
    const int warp = tid >> 5;
    const int sub  = lane & 15;        // dim-group within the 16-lane half
    const int hlf  = lane >> 4;        // which row of the pair

    __shared__ __align__(16) float  q_s[HD];
    __shared__ __align__(16) int    idx_s[TOPK];
    __shared__ __align__(16) float4 sc_s[TOPK];   // quad partial sums per score
    __shared__ __align__(16) float  red_s[4][HD];

    // Stage q row and indices
    q_s[tid] = q[((size_t)h * SQL + sq) * HD + tid];
    if (tid < TOPK) {
        idx_s[tid] = topk_indices[(size_t)sq * TOPK + tid];
    }
    __syncthreads();

    // q dims [sub*8, sub*8+8) in registers
    const float4* q4 = reinterpret_cast<const float4*>(q_s);
    const float4 qa = q4[sub * 2];
    const float4 qb = q4[sub * 2 + 1];

    const size_t hb   = (size_t)h * SKV * (HD / 2);  // head base, half2 units
    const int    base = warp * 16;

    int rows[8];   // this lane's 8 gathered row indices (t = base + 2i + hlf)

    // ---- Score phase: 8 iterations, 2 rows/iter, 4-deep prefetch ring ----
    {
        uint4 raw[4];
        #pragma unroll
        for (int j = 0; j < 4; j++) {
            rows[j] = idx_s[base + 2 * j + hlf];
            raw[j] = reinterpret_cast<const uint4*>(g_k16 + hb + (size_t)rows[j] * (HD / 2))[sub];
        }
        #pragma unroll
        for (int i = 0; i < 8; i++) {
            uint4 cur = raw[i & 3];
            if (i < 4) {
                rows[i + 4] = idx_s[base + 2 * (i + 4) + hlf];
                raw[i & 3] = reinterpret_cast<const uint4*>(g_k16 + hb + (size_t)rows[i + 4] * (HD / 2))[sub];
            }
            float2 f0 = __half22float2(*reinterpret_cast<__half2*>(&cur.x));
            float2 f1 = __half22float2(*reinterpret_cast<__half2*>(&cur.y));
            float2 f2 = __half22float2(*reinterpret_cast<__half2*>(&cur.z));
            float2 f3 = __half22float2(*reinterpret_cast<__half2*>(&cur.w));
            float p = qa.x * f0.x + qa.y * f0.y + qa.z * f1.x + qa.w * f1.y
                    + qb.x * f2.x + qb.y * f2.y + qb.z * f3.x + qb.w * f3.y;
            // 2-shfl reduce: lanes sub<4 hold the 4 quad-partials of this row
            p += __shfl_xor_sync(0xffffffffu, p, 8);
            p += __shfl_xor_sync(0xffffffffu, p, 4);
            if (sub < 4) {
                float* dst = reinterpret_cast<float*>(&sc_s[base + 2 * i + hlf]);
                dst[sub] = p;
            }
        }
    }
    __syncthreads();

    // ---- Distributed softmax (every warp, redundantly) ----
    //   w_t = e_t * p_t / (sum(e*p) + 1e-12 * sum(e))
    // Lane L keeps w[t=L] in w0 and w[t=L+32] in w1 (identical in all warps).
    float w0, w1;
    {
        const float scale = 0.088388347648318447f;  // 128^-0.5
        const float4 v0 = sc_s[lane];
        const float4 v1 = sc_s[lane + 32];
        float s0 = ((v0.x + v0.y) + (v0.z + v0.w)) * scale;
        float s1 = ((v1.x + v1.y) + (v1.z + v1.w)) * scale;
        float m = fmaxf(s0, s1);
        #pragma unroll
        for (int o = 16; o > 0; o >>= 1)
            m = fmaxf(m, __shfl_xor_sync(0xffffffffu, m, o));
        const float p0 = topk_scores[(size_t)sq * TOPK + lane];
        const float p1 = topk_scores[(size_t)sq * TOPK + lane + 32];
        const float e0 = __expf(s0 - m);
        const float e1 = __expf(s1 - m);
        w0 = e0 * p0;
        w1 = e1 * p1;
        float se = e0 + e1;
        float sw = w0 + w1;
        #pragma unroll
        for (int o = 16; o > 0; o >>= 1) {
            se += __shfl_xor_sync(0xffffffffu, se, o);
            sw += __shfl_xor_sync(0xffffffffu, sw, o);
        }
        const float inv = 1.0f / (sw + 1e-12f * se);
        w0 *= inv;
        w1 *= inv;
    }
    // warp w's entries t=16w+j live in lane 16*(w&1)+j, slot (w<2 ? w0 : w1)
    const float wsel     = (warp < 2) ? w0 : w1;
    const int   src_base = (warp & 1) * 16;

    // ---- V phase: 2 rows/LDG, 8 dims/lane, 4-deep prefetch ring ----
    float a0 = 0.f, a1 = 0.f, a2 = 0.f, a3 = 0.f;
    float a4 = 0.f, a5 = 0.f, a6 = 0.f, a7 = 0.f;
    {
        uint4 raw[4];
        #pragma unroll
        for (int j = 0; j < 4; j++) {
            raw[j] = reinterpret_cast<const uint4*>(g_v16 + hb + (size_t)rows[j] * (HD / 2))[sub];
        }
        #pragma unroll
        for (int i = 0; i < 8; i++) {
            uint4 cur = raw[i & 3];
            const float wgt = __shfl_sync(0xffffffffu, wsel, src_base + 2 * i + hlf);
            if (i < 4) {
                raw[i & 3] = reinterpret_cast<const uint4*>(g_v16 + hb + (size_t)rows[i + 4] * (HD / 2))[sub];
            }
            float2 f0 = __half22float2(*reinterpret_cast<__half2*>(&cur.x));
            float2 f1 = __half22float2(*reinterpret_cast<__half2*>(&cur.y));
            float2 f2 = __half22float2(*reinterpret_cast<__half2*>(&cur.z));
            float2 f3 = __half22float2(*reinterpret_cast<__half2*>(&cur.w));
            a0 += wgt * f0.x; a1 += wgt * f0.y;
            a2 += wgt * f1.x; a3 += wgt * f1.y;
            a4 += wgt * f2.x; a5 += wgt * f2.y;
            a6 += wgt * f3.x; a7 += wgt * f3.y;
        }
    }
    // combine the two 16-lane halves (different rows, same dims)
    a0 += __shfl_xor_sync(0xffffffffu, a0, 16);
    a1 += __shfl_xor_sync(0xffffffffu, a1, 16);
    a2 += __shfl_xor_sync(0xffffffffu, a2, 16);
    a3 += __shfl_xor_sync(0xffffffffu, a3, 16);
    a4 += __shfl_xor_sync(0xffffffffu, a4, 16);
    a5 += __shfl_xor_sync(0xffffffffu, a5, 16);
    a6 += __shfl_xor_sync(0xffffffffu, a6, 16);
    a7 += __shfl_xor_sync(0xffffffffu, a7, 16);

    if (hlf == 0) {
        float4* r4 = reinterpret_cast<float4*>(&red_s[warp][sub * 8]);
        r4[0] = make_float4(a0, a1, a2, a3);
        r4[1] = make_float4(a4, a5, a6, a7);
    }
    __syncthreads();

    // cross-warp reduce + store (thread tid owns output dim tid)
    float r = (red_s[0][tid] + red_s[1][tid]) + (red_s[2][tid] + red_s[3][tid]);
    out[((size_t)h * SQL + sq) * HD + tid] = r;
}

extern "C" void kernel_launch(void* const* d_in, const int* in_sizes, int n_in,
                              void* d_out, int out_size) {
    const float* q   = (const float*)d_in[0];
    const float* k   = (const float*)d_in[1];
    const float* v   = (const float*)d_in[2];
    const int*   ti  = (const int*)  d_in[3];
    const float* ts  = (const float*)d_in[4];
    float* out = (float*)d_out;

    const int n8 = KV_ELEMS / 8;
    convert_kv_kernel<<<n8 / 256, 256>>>((const float4*)k, (const float4*)v);

    dim3 grid(SQL, NH);
    dsa_sparse_attn_kernel<<<grid, 128>>>(q, ti, ts, out);
}

// round 12
// speedup vs baseline: 1.0249x; 1.0249x over previous
#include <cuda_runtime.h>
#include <cuda_fp16.h>

#define HD   128     // head dim
#define TOPK 64
#define SQL  1024
#define SKV  4096
#define NH   16
#define KV_ELEMS (NH * SKV * HD)   // 8,388,608 per tensor

#define NGROUPS 8
#define HPG     (NH / NGROUPS)     // heads per group = 2
#define NMAINS  4                  // streams for main launches

// fp16 copies of K and V (16 MB each)
__device__ __half2 g_k16[KV_ELEMS / 2];
__device__ __half2 g_v16[KV_ELEMS / 2];

// ---- Pre-pass: fp32 -> fp16 conversion of K and V for HPG heads ----
__global__ __launch_bounds__(256)
void convert_kv_kernel(const float4* __restrict__ k, const float4* __restrict__ v,
                       int head_off) {
    const size_t goff = (size_t)head_off * SKV * HD / 8;   // in uint4/2xfloat4 units
    const size_t i = goff + blockIdx.x * blockDim.x + threadIdx.x;
    uint4* kd = reinterpret_cast<uint4*>(g_k16);
    uint4* vd = reinterpret_cast<uint4*>(g_v16);

    float4 a0 = k[2 * i], a1 = k[2 * i + 1];
    __half2 k0 = __floats2half2_rn(a0.x, a0.y);
    __half2 k1 = __floats2half2_rn(a0.z, a0.w);
    __half2 k2 = __floats2half2_rn(a1.x, a1.y);
    __half2 k3 = __floats2half2_rn(a1.z, a1.w);
    uint4 kp;
    kp.x = *reinterpret_cast<unsigned*>(&k0);
    kp.y = *reinterpret_cast<unsigned*>(&k1);
    kp.z = *reinterpret_cast<unsigned*>(&k2);
    kp.w = *reinterpret_cast<unsigned*>(&k3);
    kd[i] = kp;

    float4 b0 = v[2 * i], b1 = v[2 * i + 1];
    __half2 v0 = __floats2half2_rn(b0.x, b0.y);
    __half2 v1 = __floats2half2_rn(b0.z, b0.w);
    __half2 v2 = __floats2half2_rn(b1.x, b1.y);
    __half2 v3 = __floats2half2_rn(b1.z, b1.w);
    uint4 vp;
    vp.x = *reinterpret_cast<unsigned*>(&v0);
    vp.y = *reinterpret_cast<unsigned*>(&v1);
    vp.z = *reinterpret_cast<unsigned*>(&v2);
    vp.w = *reinterpret_cast<unsigned*>(&v3);
    vd[i] = vp;
}

// ---- Main sparse-attention kernel (R10 body; grid.y covers HPG heads) ----
// Block = (h, sq). 4 warps; warp w owns topk entries [w*16, w*16+16).
// Lanes 0-15 process one row, lanes 16-31 a second row; each lane covers
// 8 head dims via one 16B load. 4-deep prefetch ring (MLP=4 per warp).
// V phase reads a packed (idx, weight) float2 table built by the softmax warp.
__global__ __launch_bounds__(128, 10)
void dsa_sparse_attn_kernel(const float* __restrict__ q,
                            const int*   __restrict__ topk_indices,
                            const float* __restrict__ topk_scores,
                            float* __restrict__ out,
                            int head_off) {
    const int sq   = blockIdx.x;
    const int h    = blockIdx.y + head_off;
    const int tid  = threadIdx.x;      // 0..127
    const int lane = tid & 31;
    const int warp = tid >> 5;
    const int sub  = lane & 15;        // dim-group within the 16-lane half
    const int hlf  = lane >> 4;        // which row of the pair

    __shared__ __align__(16) float  q_s[HD];
    __shared__ __align__(16) int    idx_s[TOPK];
    __shared__ __align__(16) float4 sc_s[TOPK];   // quad partial sums per score
    __shared__ __align__(16) float2 pk_s[TOPK];   // packed (idx-bits, weight)
    __shared__ __align__(16) float  red_s[4][HD];

    // Stage q row and indices
    q_s[tid] = q[((size_t)h * SQL + sq) * HD + tid];
    if (tid < TOPK) {
        idx_s[tid] = topk_indices[(size_t)sq * TOPK + tid];
    }
    __syncthreads();

    // q dims [sub*8, sub*8+8) in registers
    const float4* q4 = reinterpret_cast<const float4*>(q_s);
    const float4 qa = q4[sub * 2];
    const float4 qb = q4[sub * 2 + 1];

    const size_t hb   = (size_t)h * SKV * (HD / 2);  // head base, half2 units
    const int    base = warp * 16;

    // ---- Score phase: 8 iterations, 2 rows/iter, 4-deep prefetch ring ----
    {
        uint4 raw[4];
        #pragma unroll
        for (int j = 0; j < 4; j++) {
            const int row = idx_s[base + 2 * j + hlf];
            raw[j] = reinterpret_cast<const uint4*>(g_k16 + hb + (size_t)row * (HD / 2))[sub];
        }
        #pragma unroll
        for (int i = 0; i < 8; i++) {
            uint4 cur = raw[i & 3];
            if (i < 4) {
                const int rown = idx_s[base + 2 * (i + 4) + hlf];
                raw[i & 3] = reinterpret_cast<const uint4*>(g_k16 + hb + (size_t)rown * (HD / 2))[sub];
            }
            float2 f0 = __half22float2(*reinterpret_cast<__half2*>(&cur.x));
            float2 f1 = __half22float2(*reinterpret_cast<__half2*>(&cur.y));
            float2 f2 = __half22float2(*reinterpret_cast<__half2*>(&cur.z));
            float2 f3 = __half22float2(*reinterpret_cast<__half2*>(&cur.w));
            float p = qa.x * f0.x + qa.y * f0.y + qa.z * f1.x + qa.w * f1.y
                    + qb.x * f2.x + qb.y * f2.y + qb.z * f3.x + qb.w * f3.y;
            // 2-shfl reduce: lanes sub<4 hold the 4 quad-partials of this row
            p += __shfl_xor_sync(0xffffffffu, p, 8);
            p += __shfl_xor_sync(0xffffffffu, p, 4);
            if (sub < 4) {
                float* dst = reinterpret_cast<float*>(&sc_s[base + 2 * i + hlf]);
                dst[sub] = p;
            }
        }
    }
    __syncthreads();

    // ---- Softmax + score-weight fusion (warp 0) ----
    //   w_t = e_t * p_t / (sum(e*p) + 1e-12 * sum(e))
    if (warp == 0) {
        const float scale = 0.088388347648318447f;  // 128^-0.5
        const float4 v0 = sc_s[lane];
        const float4 v1 = sc_s[lane + 32];
        float s0 = ((v0.x + v0.y) + (v0.z + v0.w)) * scale;
        float s1 = ((v1.x + v1.y) + (v1.z + v1.w)) * scale;
        float m = fmaxf(s0, s1);
        #pragma unroll
        for (int o = 16; o > 0; o >>= 1)
            m = fmaxf(m, __shfl_xor_sync(0xffffffffu, m, o));
        const float p0 = topk_scores[(size_t)sq * TOPK + lane];
        const float p1 = topk_scores[(size_t)sq * TOPK + lane + 32];
        const float e0 = __expf(s0 - m);
        const float e1 = __expf(s1 - m);
        const float w0 = e0 * p0;
        const float w1 = e1 * p1;
        float se = e0 + e1;
        float sw = w0 + w1;
        #pragma unroll
        for (int o = 16; o > 0; o >>= 1) {
            se += __shfl_xor_sync(0xffffffffu, se, o);
            sw += __shfl_xor_sync(0xffffffffu, sw, o);
        }
        const float inv = 1.0f / (sw + 1e-12f * se);
        // build packed (idx-bits, weight) table for the V phase
        pk_s[lane]      = make_float2(__int_as_float(idx_s[lane]),      w0 * inv);
        pk_s[lane + 32] = make_float2(__int_as_float(idx_s[lane + 32]), w1 * inv);
    }
    __syncthreads();

    // ---- V phase: 2 rows/LDG, 8 dims/lane, 4-deep prefetch ring ----
    float a0 = 0.f, a1 = 0.f, a2 = 0.f, a3 = 0.f;
    float a4 = 0.f, a5 = 0.f, a6 = 0.f, a7 = 0.f;
    {
        uint4 raw[4];
        float wr[4];
        #pragma unroll
        for (int j = 0; j < 4; j++) {
            const float2 pk = pk_s[base + 2 * j + hlf];
            const int row = __float_as_int(pk.x);
            wr[j] = pk.y;
            raw[j] = reinterpret_cast<const uint4*>(g_v16 + hb + (size_t)row * (HD / 2))[sub];
        }
        #pragma unroll
        for (int i = 0; i < 8; i++) {
            uint4 cur = raw[i & 3];
            float wgt = wr[i & 3];
            if (i < 4) {
                const float2 pk = pk_s[base + 2 * (i + 4) + hlf];
                const int rown = __float_as_int(pk.x);
                wr[i & 3] = pk.y;
                raw[i & 3] = reinterpret_cast<const uint4*>(g_v16 + hb + (size_t)rown * (HD / 2))[sub];
            }
            float2 f0 = __half22float2(*reinterpret_cast<__half2*>(&cur.x));
            float2 f1 = __half22float2(*reinterpret_cast<__half2*>(&cur.y));
            float2 f2 = __half22float2(*reinterpret_cast<__half2*>(&cur.z));
            float2 f3 = __half22float2(*reinterpret_cast<__half2*>(&cur.w));
            a0 += wgt * f0.x; a1 += wgt * f0.y;
            a2 += wgt * f1.x; a3 += wgt * f1.y;
            a4 += wgt * f2.x; a5 += wgt * f2.y;
            a6 += wgt * f3.x; a7 += wgt * f3.y;
        }
    }
    // combine the two 16-lane halves (different rows, same dims)
    a0 += __shfl_xor_sync(0xffffffffu, a0, 16);
    a1 += __shfl_xor_sync(0xffffffffu, a1, 16);
    a2 += __shfl_xor_sync(0xffffffffu, a2, 16);
    a3 += __shfl_xor_sync(0xffffffffu, a3, 16);
    a4 += __shfl_xor_sync(0xffffffffu, a4, 16);
    a5 += __shfl_xor_sync(0xffffffffu, a5, 16);
    a6 += __shfl_xor_sync(0xffffffffu, a6, 16);
    a7 += __shfl_xor_sync(0xffffffffu, a7, 16);

    if (hlf == 0) {
        float4* r4 = reinterpret_cast<float4*>(&red_s[warp][sub * 8]);
        r4[0] = make_float4(a0, a1, a2, a3);
        r4[1] = make_float4(a4, a5, a6, a7);
    }
    __syncthreads();

    // cross-warp reduce + store (thread tid owns output dim tid)
    float r = (red_s[0][tid] + red_s[1][tid]) + (red_s[2][tid] + red_s[3][tid]);
    out[((size_t)h * SQL + sq) * HD + tid] = r;
}

// ---- Streams/events for graph-captured pipelining (created once at load;
//      no device memory, no per-call guards) ----
struct PipeRes {
    cudaStream_t sConv;
    cudaStream_t sMain[NMAINS];
    cudaEvent_t  evRoot;
    cudaEvent_t  evConv[NGROUPS];
    cudaEvent_t  evDone[NMAINS];
    PipeRes() {
        cudaStreamCreateWithFlags(&sConv, cudaStreamNonBlocking);
        for (int i = 0; i < NMAINS; i++)
            cudaStreamCreateWithFlags(&sMain[i], cudaStreamNonBlocking);
        cudaEventCreateWithFlags(&evRoot, cudaEventDisableTiming);
        for (int i = 0; i < NGROUPS; i++)
            cudaEventCreateWithFlags(&evConv[i], cudaEventDisableTiming);
        for (int i = 0; i < NMAINS; i++)
            cudaEventCreateWithFlags(&evDone[i], cudaEventDisableTiming);
    }
};
static PipeRes g_pipe;

extern "C" void kernel_launch(void* const* d_in, const int* in_sizes, int n_in,
                              void* d_out, int out_size) {
    const float* q   = (const float*)d_in[0];
    const float* k   = (const float*)d_in[1];
    const float* v   = (const float*)d_in[2];
    const int*   ti  = (const int*)  d_in[3];
    const float* ts  = (const float*)d_in[4];
    float* out = (float*)d_out;

    // Fork converter stream from the capture-origin (default) stream.
    cudaEventRecord(g_pipe.evRoot, 0);
    cudaStreamWaitEvent(g_pipe.sConv, g_pipe.evRoot, 0);

    const int conv_blocks = (HPG * SKV * HD / 8) / 256;   // 512

    for (int g = 0; g < NGROUPS; g++) {
        convert_kv_kernel<<<conv_blocks, 256, 0, g_pipe.sConv>>>(
            (const float4*)k, (const float4*)v, g * HPG);
        cudaEventRecord(g_pipe.evConv[g], g_pipe.sConv);
    }

    for (int g = 0; g < NGROUPS; g++) {
        cudaStream_t s = g_pipe.sMain[g % NMAINS];
        cudaStreamWaitEvent(s, g_pipe.evConv[g], 0);
        dim3 grid(SQL, HPG);
        dsa_sparse_attn_kernel<<<grid, 128, 0, s>>>(q, ti, ts, out, g * HPG);
    }

    // Join all main streams back into the default stream.
    for (int i = 0; i < NMAINS; i++) {
        cudaEventRecord(g_pipe.evDone[i], g_pipe.sMain[i]);
        cudaStreamWaitEvent(0, g_pipe.evDone[i], 0);
    }
}

// round 13
// speedup vs baseline: 1.0425x; 1.0172x over previous
#include <cuda_runtime.h>
#include <cuda_fp16.h>

#define HD   128     // head dim
#define TOPK 64
#define SQL  1024
#define SKV  4096
#define NH   16
#define KV_ELEMS (NH * SKV * HD)   // 8,388,608 per tensor

#define NGROUPS 8
#define HPG     (NH / NGROUPS)     // heads per group = 2
#define NMAINS  4                  // streams for main launches

// fp16 copies of K and V (16 MB each)
__device__ __half2 g_k16[KV_ELEMS / 2];
__device__ __half2 g_v16[KV_ELEMS / 2];

// ---- Pre-pass: fp32 -> fp16 conversion for HPG heads, 4 elems/thread ----
// (4 elems/thread = 2x the thread count of the 8-elem version; restores the
//  DRAM MLP that the chunked R12 converts lost -- they ran at 1.6 TB/s.)
__global__ __launch_bounds__(256)
void convert_kv_kernel(const float4* __restrict__ k, const float4* __restrict__ v,
                       int head_off) {
    const size_t goff = (size_t)head_off * SKV * HD / 4;   // in float4 units
    const size_t i = goff + blockIdx.x * blockDim.x + threadIdx.x;
    uint2* kd = reinterpret_cast<uint2*>(g_k16);
    uint2* vd = reinterpret_cast<uint2*>(g_v16);

    float4 a = k[i];
    float4 b = v[i];

    __half2 k0 = __floats2half2_rn(a.x, a.y);
    __half2 k1 = __floats2half2_rn(a.z, a.w);
    uint2 kp;
    kp.x = *reinterpret_cast<unsigned*>(&k0);
    kp.y = *reinterpret_cast<unsigned*>(&k1);
    kd[i] = kp;

    __half2 v0 = __floats2half2_rn(b.x, b.y);
    __half2 v1 = __floats2half2_rn(b.z, b.w);
    uint2 vp;
    vp.x = *reinterpret_cast<unsigned*>(&v0);
    vp.y = *reinterpret_cast<unsigned*>(&v1);
    vd[i] = vp;
}

// ---- Main sparse-attention kernel (R10 body; grid.y covers HPG heads) ----
// Block = (h, sq). 4 warps; warp w owns topk entries [w*16, w*16+16).
// Lanes 0-15 process one row, lanes 16-31 a second row; each lane covers
// 8 head dims via one 16B load. 4-deep prefetch ring (MLP=4 per warp).
// V phase reads a packed (idx, weight) float2 table built by the softmax warp.
__global__ __launch_bounds__(128, 10)
void dsa_sparse_attn_kernel(const float* __restrict__ q,
                            const int*   __restrict__ topk_indices,
                            const float* __restrict__ topk_scores,
                            float* __restrict__ out,
                            int head_off) {
    const int sq   = blockIdx.x;
    const int h    = blockIdx.y + head_off;
    const int tid  = threadIdx.x;      // 0..127
    const int lane = tid & 31;
    const int warp = tid >> 5;
    const int sub  = lane & 15;        // dim-group within the 16-lane half
    const int hlf  = lane >> 4;        // which row of the pair

    __shared__ __align__(16) float  q_s[HD];
    __shared__ __align__(16) int    idx_s[TOPK];
    __shared__ __align__(16) float4 sc_s[TOPK];   // quad partial sums per score
    __shared__ __align__(16) float2 pk_s[TOPK];   // packed (idx-bits, weight)
    __shared__ __align__(16) float  red_s[4][HD];

    // Stage q row and indices
    q_s[tid] = q[((size_t)h * SQL + sq) * HD + tid];
    if (tid < TOPK) {
        idx_s[tid] = topk_indices[(size_t)sq * TOPK + tid];
    }
    __syncthreads();

    // q dims [sub*8, sub*8+8) in registers
    const float4* q4 = reinterpret_cast<const float4*>(q_s);
    const float4 qa = q4[sub * 2];
    const float4 qb = q4[sub * 2 + 1];

    const size_t hb   = (size_t)h * SKV * (HD / 2);  // head base, half2 units
    const int    base = warp * 16;

    // ---- Score phase: 8 iterations, 2 rows/iter, 4-deep prefetch ring ----
    {
        uint4 raw[4];
        #pragma unroll
        for (int j = 0; j < 4; j++) {
            const int row = idx_s[base + 2 * j + hlf];
            raw[j] = reinterpret_cast<const uint4*>(g_k16 + hb + (size_t)row * (HD / 2))[sub];
        }
        #pragma unroll
        for (int i = 0; i < 8; i++) {
            uint4 cur = raw[i & 3];
            if (i < 4) {
                const int rown = idx_s[base + 2 * (i + 4) + hlf];
                raw[i & 3] = reinterpret_cast<const uint4*>(g_k16 + hb + (size_t)rown * (HD / 2))[sub];
            }
            float2 f0 = __half22float2(*reinterpret_cast<__half2*>(&cur.x));
            float2 f1 = __half22float2(*reinterpret_cast<__half2*>(&cur.y));
            float2 f2 = __half22float2(*reinterpret_cast<__half2*>(&cur.z));
            float2 f3 = __half22float2(*reinterpret_cast<__half2*>(&cur.w));
            float p = qa.x * f0.x + qa.y * f0.y + qa.z * f1.x + qa.w * f1.y
                    + qb.x * f2.x + qb.y * f2.y + qb.z * f3.x + qb.w * f3.y;
            // 2-shfl reduce: lanes sub<4 hold the 4 quad-partials of this row
            p += __shfl_xor_sync(0xffffffffu, p, 8);
            p += __shfl_xor_sync(0xffffffffu, p, 4);
            if (sub < 4) {
                float* dst = reinterpret_cast<float*>(&sc_s[base + 2 * i + hlf]);
                dst[sub] = p;
            }
        }
    }
    __syncthreads();

    // ---- Softmax + score-weight fusion (warp 0) ----
    //   w_t = e_t * p_t / (sum(e*p) + 1e-12 * sum(e))
    if (warp == 0) {
        const float scale = 0.088388347648318447f;  // 128^-0.5
        const float4 v0 = sc_s[lane];
        const float4 v1 = sc_s[lane + 32];
        float s0 = ((v0.x + v0.y) + (v0.z + v0.w)) * scale;
        float s1 = ((v1.x + v1.y) + (v1.z + v1.w)) * scale;
        float m = fmaxf(s0, s1);
        #pragma unroll
        for (int o = 16; o > 0; o >>= 1)
            m = fmaxf(m, __shfl_xor_sync(0xffffffffu, m, o));
        const float p0 = topk_scores[(size_t)sq * TOPK + lane];
        const float p1 = topk_scores[(size_t)sq * TOPK + lane + 32];
        const float e0 = __expf(s0 - m);
        const float e1 = __expf(s1 - m);
        const float w0 = e0 * p0;
        const float w1 = e1 * p1;
        float se = e0 + e1;
        float sw = w0 + w1;
        #pragma unroll
        for (int o = 16; o > 0; o >>= 1) {
            se += __shfl_xor_sync(0xffffffffu, se, o);
            sw += __shfl_xor_sync(0xffffffffu, sw, o);
        }
        const float inv = 1.0f / (sw + 1e-12f * se);
        // build packed (idx-bits, weight) table for the V phase
        pk_s[lane]      = make_float2(__int_as_float(idx_s[lane]),      w0 * inv);
        pk_s[lane + 32] = make_float2(__int_as_float(idx_s[lane + 32]), w1 * inv);
    }
    __syncthreads();

    // ---- V phase: 2 rows/LDG, 8 dims/lane, 4-deep prefetch ring ----
    float a0 = 0.f, a1 = 0.f, a2 = 0.f, a3 = 0.f;
    float a4 = 0.f, a5 = 0.f, a6 = 0.f, a7 = 0.f;
    {
        uint4 raw[4];
        float wr[4];
        #pragma unroll
        for (int j = 0; j < 4; j++) {
            const float2 pk = pk_s[base + 2 * j + hlf];
            const int row = __float_as_int(pk.x);
            wr[j] = pk.y;
            raw[j] = reinterpret_cast<const uint4*>(g_v16 + hb + (size_t)row * (HD / 2))[sub];
        }
        #pragma unroll
        for (int i = 0; i < 8; i++) {
            uint4 cur = raw[i & 3];
            float wgt = wr[i & 3];
            if (i < 4) {
                const float2 pk = pk_s[base + 2 * (i + 4) + hlf];
                const int rown = __float_as_int(pk.x);
                wr[i & 3] = pk.y;
                raw[i & 3] = reinterpret_cast<const uint4*>(g_v16 + hb + (size_t)rown * (HD / 2))[sub];
            }
            float2 f0 = __half22float2(*reinterpret_cast<__half2*>(&cur.x));
            float2 f1 = __half22float2(*reinterpret_cast<__half2*>(&cur.y));
            float2 f2 = __half22float2(*reinterpret_cast<__half2*>(&cur.z));
            float2 f3 = __half22float2(*reinterpret_cast<__half2*>(&cur.w));
            a0 += wgt * f0.x; a1 += wgt * f0.y;
            a2 += wgt * f1.x; a3 += wgt * f1.y;
            a4 += wgt * f2.x; a5 += wgt * f2.y;
            a6 += wgt * f3.x; a7 += wgt * f3.y;
        }
    }
    // combine the two 16-lane halves (different rows, same dims)
    a0 += __shfl_xor_sync(0xffffffffu, a0, 16);
    a1 += __shfl_xor_sync(0xffffffffu, a1, 16);
    a2 += __shfl_xor_sync(0xffffffffu, a2, 16);
    a3 += __shfl_xor_sync(0xffffffffu, a3, 16);
    a4 += __shfl_xor_sync(0xffffffffu, a4, 16);
    a5 += __shfl_xor_sync(0xffffffffu, a5, 16);
    a6 += __shfl_xor_sync(0xffffffffu, a6, 16);
    a7 += __shfl_xor_sync(0xffffffffu, a7, 16);

    if (hlf == 0) {
        float4* r4 = reinterpret_cast<float4*>(&red_s[warp][sub * 8]);
        r4[0] = make_float4(a0, a1, a2, a3);
        r4[1] = make_float4(a4, a5, a6, a7);
    }
    __syncthreads();

    // cross-warp reduce + store (thread tid owns output dim tid)
    float r = (red_s[0][tid] + red_s[1][tid]) + (red_s[2][tid] + red_s[3][tid]);
    out[((size_t)h * SQL + sq) * HD + tid] = r;
}

// ---- Streams/events for graph-captured pipelining (created once at load;
//      no device memory, no per-call guards) ----
struct PipeRes {
    cudaStream_t sConv;
    cudaStream_t sMain[NMAINS];
    cudaEvent_t  evRoot;
    cudaEvent_t  evConv[NGROUPS];
    cudaEvent_t  evDone[NMAINS];
    PipeRes() {
        cudaStreamCreateWithFlags(&sConv, cudaStreamNonBlocking);
        for (int i = 0; i < NMAINS; i++)
            cudaStreamCreateWithFlags(&sMain[i], cudaStreamNonBlocking);
        cudaEventCreateWithFlags(&evRoot, cudaEventDisableTiming);
        for (int i = 0; i < NGROUPS; i++)
            cudaEventCreateWithFlags(&evConv[i], cudaEventDisableTiming);
        for (int i = 0; i < NMAINS; i++)
            cudaEventCreateWithFlags(&evDone[i], cudaEventDisableTiming);
    }
};
static PipeRes g_pipe;

extern "C" void kernel_launch(void* const* d_in, const int* in_sizes, int n_in,
                              void* d_out, int out_size) {
    const float* q   = (const float*)d_in[0];
    const float* k   = (const float*)d_in[1];
    const float* v   = (const float*)d_in[2];
    const int*   ti  = (const int*)  d_in[3];
    const float* ts  = (const float*)d_in[4];
    float* out = (float*)d_out;

    // Fork converter stream from the capture-origin (default) stream.
    cudaEventRecord(g_pipe.evRoot, 0);
    cudaStreamWaitEvent(g_pipe.sConv, g_pipe.evRoot, 0);

    const int conv_blocks = (HPG * SKV * HD / 4) / 256;   // 1024

    for (int g = 0; g < NGROUPS; g++) {
        convert_kv_kernel<<<conv_blocks, 256, 0, g_pipe.sConv>>>(
            (const float4*)k, (const float4*)v, g * HPG);
        cudaEventRecord(g_pipe.evConv[g], g_pipe.sConv);
    }

    for (int g = 0; g < NGROUPS; g++) {
        cudaStream_t s = g_pipe.sMain[g % NMAINS];
        cudaStreamWaitEvent(s, g_pipe.evConv[g], 0);
        dim3 grid(SQL, HPG);
        dsa_sparse_attn_kernel<<<grid, 128, 0, s>>>(q, ti, ts, out, g * HPG);
    }

    // Join all main streams back into the default stream.
    for (int i = 0; i < NMAINS; i++) {
        cudaEventRecord(g_pipe.evDone[i], g_pipe.sMain[i]);
        cudaStreamWaitEvent(0, g_pipe.evDone[i], 0);
    }
}